// round 8
// baseline (speedup 1.0000x reference)
#include <cuda_runtime.h>
#include <cuda_fp16.h>
#include <cstdint>

constexpr int Hh = 8, DH = 64, INNER = 512, QLEN = 4096, KLEN = 308, CL = 77;
constexpr int QT = 128, NQT = 32, TPB = 256;
constexpr int LDH = 72;                     // halves per smem row (144B, ldmatrix conflict-free)
constexpr int KROWS = 312;                  // 308 + 4 pad rows (zeroed)

// device scratch
__device__ __half g_kh[2 * KLEN * INNER];
__device__ __half g_vh[2 * KLEN * INNER];
__device__ float  g_cs[4];                  // (128/sum)*log2(e)
__device__ unsigned char g_act[QLEN];

// smem: Q + full K + full V
constexpr int OFF_QH = 0;
constexpr int OFF_K  = OFF_QH + QT * LDH * 2;       // 18432
constexpr int OFF_V  = OFF_K + KROWS * LDH * 2;     // 63360
constexpr int SMEM_BYTES = OFF_V + KROWS * LDH * 2; // 108288 -> 2 CTAs/SM

__device__ __forceinline__ uint32_t h2u(float a, float b) {
    __half2 h = __floats2half2_rn(a, b);
    return *reinterpret_cast<uint32_t*>(&h);
}
__device__ __forceinline__ float ex2(float x) {
    float r; asm("ex2.approx.f32 %0, %1;" : "=f"(r) : "f"(x)); return r;
}
__device__ __forceinline__ void ldsm_x4(uint32_t* r, uint32_t addr) {
    asm volatile("ldmatrix.sync.aligned.m8n8.x4.shared.b16 {%0,%1,%2,%3}, [%4];"
                 : "=r"(r[0]), "=r"(r[1]), "=r"(r[2]), "=r"(r[3]) : "r"(addr));
}
__device__ __forceinline__ void ldsm_x4_t(uint32_t* r, uint32_t addr) {
    asm volatile("ldmatrix.sync.aligned.m8n8.x4.trans.shared.b16 {%0,%1,%2,%3}, [%4];"
                 : "=r"(r[0]), "=r"(r[1]), "=r"(r[2]), "=r"(r[3]) : "r"(addr));
}
__device__ __forceinline__ void mma16816(float* c, const uint32_t* a, uint32_t b0, uint32_t b1) {
    asm volatile("mma.sync.aligned.m16n8k16.row.col.f32.f16.f16.f32 "
                 "{%0,%1,%2,%3},{%4,%5,%6,%7},{%8,%9},{%0,%1,%2,%3};"
                 : "+f"(c[0]), "+f"(c[1]), "+f"(c[2]), "+f"(c[3])
                 : "r"(a[0]), "r"(a[1]), "r"(a[2]), "r"(a[3]), "r"(b0), "r"(b1));
}
__device__ __forceinline__ void cpa16(uint32_t s, const void* g) {
    asm volatile("cp.async.cg.shared.global [%0], [%1], 16;" :: "r"(s), "l"(g));
}

// ---------------------------------------------------------------------------
// prep: K,V -> fp16; region scales (x log2e); per-query activity bytes
// ---------------------------------------------------------------------------
__global__ void __launch_bounds__(256) prep_kernel(const float* __restrict__ k,
                                                   const float* __restrict__ v,
                                                   const float* __restrict__ dd)
{
    int blk = blockIdx.x, tid = threadIdx.x;
    if (blk < 308) {
        int idx = (blk * 256 + tid) * 4;               // over 2*308*512 floats
        float4 kf = *reinterpret_cast<const float4*>(k + idx);
        float4 vf = *reinterpret_cast<const float4*>(v + idx);
        *reinterpret_cast<uint2*>(reinterpret_cast<char*>(g_kh) + (size_t)idx * 2) =
            make_uint2(h2u(kf.x, kf.y), h2u(kf.z, kf.w));
        *reinterpret_cast<uint2*>(reinterpret_cast<char*>(g_vh) + (size_t)idx * 2) =
            make_uint2(h2u(vf.x, vf.y), h2u(vf.z, vf.w));
    } else if (blk == 308) {
        __shared__ float ws[4][8];
        int w = tid >> 5, l = tid & 31;
        #pragma unroll
        for (int r = 0; r < 4; r++) {
            float s = 0.f;
            #pragma unroll
            for (int i = 0; i < 4; i++) s += dd[r * 1024 + i * 256 + tid];
            #pragma unroll
            for (int o = 16; o > 0; o >>= 1) s += __shfl_xor_sync(0xffffffffu, s, o, 32);
            if (l == 0) ws[r][w] = s;
        }
        __syncthreads();
        if (tid < 4) {
            float s = 0.f;
            #pragma unroll
            for (int ww = 0; ww < 8; ww++) s += ws[tid][ww];
            g_cs[tid] = (128.f / s) * 1.4426950408889634f;
        }
    } else {
        int qg = (blk - 309) * 256 + tid;              // 16 blocks -> 4096
        int y = qg >> 6, x = qg & 63;
        unsigned a = 0;
        #pragma unroll
        for (int r = 0; r < 4; r++)
            if (dd[r * 1024 + (y >> 1) * 32 + (x >> 1)] > 0.5f) a |= 1u << r;
        g_act[qg] = (unsigned char)a;
    }
}

// ---------------------------------------------------------------------------
// main: fp16 MMA attention; whole K/V resident; NO in-loop barriers
// ---------------------------------------------------------------------------
__global__ void __launch_bounds__(TPB, 2)
ddca_kernel(const float* __restrict__ q, float* __restrict__ out)
{
    extern __shared__ char smc[];
    half* Qh = (half*)(smc + OFF_QH);
    uint32_t sbase = (uint32_t)__cvta_generic_to_shared(smc);
    const uint32_t qh_b = sbase + OFF_QH;
    const uint32_t k_b  = sbase + OFF_K;
    const uint32_t v_b  = sbase + OFF_V;

    const int tid = threadIdx.x, w = tid >> 5, lane = tid & 31;
    const int gid = lane >> 2, tig = lane & 3;
    const int bid = blockIdx.x;
    const int qt = bid & 31, bh = bid >> 5, h = bh & 7, b = bh >> 3;

    const float* qp = q + ((size_t)b * QLEN + (size_t)qt * QT) * INNER + h * DH;
    const size_t kvbase = (size_t)b * KLEN * INNER + h * DH;

    // zero K/V pad rows 308..311 (4 rows * 144B = 144 words each array)
    if (tid < 144) {
        reinterpret_cast<uint32_t*>(smc + OFF_K + 308 * LDH * 2)[tid] = 0;
        reinterpret_cast<uint32_t*>(smc + OFF_V + 308 * LDH * 2)[tid] = 0;
    }

    // one-shot stage of ALL K and V rows via cp.async (L2-resident after prep)
    for (int i = tid; i < KLEN * 8; i += TPB) {
        int kk = i >> 3, d8 = (i & 7) * 8;
        size_t off = kvbase + (size_t)kk * INNER + d8;
        uint32_t so = (uint32_t)(kk * LDH + d8) * 2;
        cpa16(k_b + so, g_kh + off);
        cpa16(v_b + so, g_vh + off);
    }
    asm volatile("cp.async.commit_group;");

    // stage Q (fp16 rounded) via regular stores
    #pragma unroll
    for (int it = 0; it < 8; it++) {
        int i4 = tid + it * TPB;
        int row = i4 >> 4, dq = (i4 & 15) * 4;
        float4 t = *reinterpret_cast<const float4*>(qp + (size_t)row * INNER + dq);
        *reinterpret_cast<uint2*>(Qh + row * LDH + dq) =
            make_uint2(h2u(t.x, t.y), h2u(t.z, t.w));
    }

    const unsigned a0 = g_act[qt * QT + 16 * w + gid];
    const unsigned a1 = g_act[qt * QT + 16 * w + gid + 8];
    float csr[4];
    #pragma unroll
    for (int r = 0; r < 4; r++) csr[r] = g_cs[r];

    const int qrow  = 16 * w + (lane & 15);
    const int qcol0 = (lane >> 4) << 3;
    const int krow  = (lane & 7) + ((lane >> 4) << 3);
    const int kcol0 = ((lane >> 3) & 1) << 3;

    asm volatile("cp.async.wait_group 0;");
    __syncthreads();   // the ONLY barrier: Q + K + V all visible

    // Q fragments resident in registers for all 4 chunks
    uint32_t qf[4][4];
    #pragma unroll
    for (int kt = 0; kt < 4; kt++)
        ldsm_x4(qf[kt], qh_b + (uint32_t)(qrow * LDH + 16 * kt + qcol0) * 2);

    float O[8][4];
    #pragma unroll
    for (int n = 0; n < 8; n++)
        #pragma unroll
        for (int e = 0; e < 4; e++) O[n][e] = 0.f;
    float L0 = 0.f, L1 = 0.f;

    // boundary predicates: chunk-local col 72+2*tig(+1) < 77 (only j==9 tile)
    const bool bk0 = (tig <= 2), bk1 = (tig < 2);

    #pragma unroll 1
    for (int c = 0; c < 4; c++) {
        const int rbase = c * CL;                 // chunk's first K/V row

        // ---- S = Q K^T ----
        float S[10][4];
        #pragma unroll
        for (int j = 0; j < 10; j++)
            #pragma unroll
            for (int e = 0; e < 4; e++) S[j][e] = 0.f;
        #pragma unroll
        for (int kt = 0; kt < 4; kt++) {
            #pragma unroll
            for (int np = 0; np < 5; np++) {
                uint32_t bhf[4];
                ldsm_x4(bhf, k_b + (uint32_t)((rbase + 16 * np + krow) * LDH + 16 * kt + kcol0) * 2);
                mma16816(S[2 * np],     qf[kt], bhf[0], bhf[1]);
                mma16816(S[2 * np + 1], qf[kt], bhf[2], bhf[3]);
            }
        }

        // ---- P = 2^(S*cf*log2e - 8), masked; accumulate L ----
        const float c2 = csr[c];
        const bool r0a = (a0 >> c) & 1, r1a = (a1 >> c) & 1;
        uint32_t pA[5][4];
        #pragma unroll
        for (int kt2 = 0; kt2 < 5; kt2++) {
            int j0 = 2 * kt2, j1 = 2 * kt2 + 1;
            bool o10 = (j1 < 9) || bk0, o11 = (j1 < 9) || bk1;
            float e00 = r0a          ? ex2(fmaf(S[j0][0], c2, -8.f)) : 0.f;
            float e01 = r0a          ? ex2(fmaf(S[j0][1], c2, -8.f)) : 0.f;
            float e02 = r1a          ? ex2(fmaf(S[j0][2], c2, -8.f)) : 0.f;
            float e03 = r1a          ? ex2(fmaf(S[j0][3], c2, -8.f)) : 0.f;
            float e10 = (r0a && o10) ? ex2(fmaf(S[j1][0], c2, -8.f)) : 0.f;
            float e11 = (r0a && o11) ? ex2(fmaf(S[j1][1], c2, -8.f)) : 0.f;
            float e12 = (r1a && o10) ? ex2(fmaf(S[j1][2], c2, -8.f)) : 0.f;
            float e13 = (r1a && o11) ? ex2(fmaf(S[j1][3], c2, -8.f)) : 0.f;
            L0 += (e00 + e01) + (e10 + e11);
            L1 += (e02 + e03) + (e12 + e13);
            pA[kt2][0] = h2u(e00, e01);
            pA[kt2][1] = h2u(e02, e03);
            pA[kt2][2] = h2u(e10, e11);
            pA[kt2][3] = h2u(e12, e13);
        }

        // ---- O += P V ----
        #pragma unroll
        for (int kt2 = 0; kt2 < 5; kt2++) {
            #pragma unroll
            for (int dp = 0; dp < 4; dp++) {
                uint32_t vf[4];
                ldsm_x4_t(vf, v_b + (uint32_t)((rbase + 16 * kt2 + krow) * LDH + 16 * dp + kcol0) * 2);
                mma16816(O[2 * dp],     pA[kt2], vf[0], vf[2]);
                mma16816(O[2 * dp + 1], pA[kt2], vf[1], vf[3]);
            }
        }
    }

    // ---- final L reduction across the 4 tig lanes; write out ----
    L0 += __shfl_xor_sync(0xffffffffu, L0, 1);
    L0 += __shfl_xor_sync(0xffffffffu, L0, 2);
    L1 += __shfl_xor_sync(0xffffffffu, L1, 1);
    L1 += __shfl_xor_sync(0xffffffffu, L1, 2);
    const float i0 = 1.f / L0, i1 = 1.f / L1;
    float* o0 = out + ((size_t)b * QLEN + (size_t)qt * QT + 16 * w + gid) * INNER + h * DH + 2 * tig;
    float* o1 = o0 + (size_t)8 * INNER;
    #pragma unroll
    for (int n = 0; n < 8; n++) {
        *reinterpret_cast<float2*>(o0 + 8 * n) = make_float2(O[n][0] * i0, O[n][1] * i0);
        *reinterpret_cast<float2*>(o1 + 8 * n) = make_float2(O[n][2] * i1, O[n][3] * i1);
    }
}

extern "C" void kernel_launch(void* const* d_in, const int* in_sizes, int n_in,
                              void* d_out, int out_size) {
    const float* q  = (const float*)d_in[0];
    const float* k  = (const float*)d_in[1];
    const float* v  = (const float*)d_in[2];
    const float* dd = (const float*)d_in[3];
    float* out = (float*)d_out;

    prep_kernel<<<325, 256>>>(k, v, dd);

    cudaFuncSetAttribute(ddca_kernel,
                         cudaFuncAttributeMaxDynamicSharedMemorySize, SMEM_BYTES);
    ddca_kernel<<<512, TPB, SMEM_BYTES>>>(q, out);
}

// round 9
// speedup vs baseline: 1.2955x; 1.2955x over previous
#include <cuda_runtime.h>
#include <cuda_fp16.h>
#include <cstdint>

constexpr int Hh = 8, DH = 64, INNER = 512, QLEN = 4096, KLEN = 308, CL = 77, CP = 80;
constexpr int QT = 128, NQT = 32, TPB = 256;
constexpr int LDH = 72;                     // halves per smem row (144B, ldmatrix conflict-free)

// device scratch
__device__ __half g_kh[2 * KLEN * INNER];
__device__ __half g_vh[2 * KLEN * INNER];
__device__ float  g_cs[4];                  // (128/sum)*log2(e)
__device__ unsigned char g_act[QLEN];

// smem: Q + 4 dedicated K/V chunk buffers
constexpr int KV_BYTES = CP * LDH * 2;              // 11520
constexpr int OFF_QH = 0;
constexpr int OFF_KV = OFF_QH + QT * LDH * 2;       // 18432; chunk c: K at OFF_KV+c*2*KV, V at +KV
constexpr int SMEM_BYTES = OFF_KV + 8 * KV_BYTES;   // 110592 -> 2 CTAs/SM

__device__ __forceinline__ uint32_t h2u(float a, float b) {
    __half2 h = __floats2half2_rn(a, b);
    return *reinterpret_cast<uint32_t*>(&h);
}
__device__ __forceinline__ float ex2(float x) {
    float r; asm("ex2.approx.f32 %0, %1;" : "=f"(r) : "f"(x)); return r;
}
__device__ __forceinline__ void ldsm_x4(uint32_t* r, uint32_t addr) {
    asm volatile("ldmatrix.sync.aligned.m8n8.x4.shared.b16 {%0,%1,%2,%3}, [%4];"
                 : "=r"(r[0]), "=r"(r[1]), "=r"(r[2]), "=r"(r[3]) : "r"(addr));
}
__device__ __forceinline__ void ldsm_x4_t(uint32_t* r, uint32_t addr) {
    asm volatile("ldmatrix.sync.aligned.m8n8.x4.trans.shared.b16 {%0,%1,%2,%3}, [%4];"
                 : "=r"(r[0]), "=r"(r[1]), "=r"(r[2]), "=r"(r[3]) : "r"(addr));
}
__device__ __forceinline__ void mma16816(float* c, const uint32_t* a, uint32_t b0, uint32_t b1) {
    asm volatile("mma.sync.aligned.m16n8k16.row.col.f32.f16.f16.f32 "
                 "{%0,%1,%2,%3},{%4,%5,%6,%7},{%8,%9},{%0,%1,%2,%3};"
                 : "+f"(c[0]), "+f"(c[1]), "+f"(c[2]), "+f"(c[3])
                 : "r"(a[0]), "r"(a[1]), "r"(a[2]), "r"(a[3]), "r"(b0), "r"(b1));
}
__device__ __forceinline__ void cpa16(uint32_t s, const void* g) {
    asm volatile("cp.async.cg.shared.global [%0], [%1], 16;" :: "r"(s), "l"(g));
}

// ---------------------------------------------------------------------------
// prep: K,V -> fp16; region scales (x log2e); per-query activity bytes
// ---------------------------------------------------------------------------
__global__ void __launch_bounds__(256) prep_kernel(const float* __restrict__ k,
                                                   const float* __restrict__ v,
                                                   const float* __restrict__ dd)
{
    int blk = blockIdx.x, tid = threadIdx.x;
    if (blk < 308) {
        int idx = (blk * 256 + tid) * 4;               // over 2*308*512 floats
        float4 kf = *reinterpret_cast<const float4*>(k + idx);
        float4 vf = *reinterpret_cast<const float4*>(v + idx);
        *reinterpret_cast<uint2*>(reinterpret_cast<char*>(g_kh) + (size_t)idx * 2) =
            make_uint2(h2u(kf.x, kf.y), h2u(kf.z, kf.w));
        *reinterpret_cast<uint2*>(reinterpret_cast<char*>(g_vh) + (size_t)idx * 2) =
            make_uint2(h2u(vf.x, vf.y), h2u(vf.z, vf.w));
    } else if (blk == 308) {
        __shared__ float ws[4][8];
        int w = tid >> 5, l = tid & 31;
        #pragma unroll
        for (int r = 0; r < 4; r++) {
            float s = 0.f;
            #pragma unroll
            for (int i = 0; i < 4; i++) s += dd[r * 1024 + i * 256 + tid];
            #pragma unroll
            for (int o = 16; o > 0; o >>= 1) s += __shfl_xor_sync(0xffffffffu, s, o, 32);
            if (l == 0) ws[r][w] = s;
        }
        __syncthreads();
        if (tid < 4) {
            float s = 0.f;
            #pragma unroll
            for (int ww = 0; ww < 8; ww++) s += ws[tid][ww];
            g_cs[tid] = (128.f / s) * 1.4426950408889634f;
        }
    } else {
        int qg = (blk - 309) * 256 + tid;              // 16 blocks -> 4096
        int y = qg >> 6, x = qg & 63;
        unsigned a = 0;
        #pragma unroll
        for (int r = 0; r < 4; r++)
            if (dd[r * 1024 + (y >> 1) * 32 + (x >> 1)] > 0.5f) a |= 1u << r;
        g_act[qg] = (unsigned char)a;
    }
}

// ---------------------------------------------------------------------------
// main: fp16 MMA attention; 4 dedicated buffers, grouped cp.async waits
// ---------------------------------------------------------------------------
__global__ void __launch_bounds__(TPB, 2)
ddca_kernel(const float* __restrict__ q, float* __restrict__ out)
{
    extern __shared__ char smc[];
    half* Qh = (half*)(smc + OFF_QH);
    uint32_t sbase = (uint32_t)__cvta_generic_to_shared(smc);
    const uint32_t qh_b = sbase + OFF_QH;

    const int tid = threadIdx.x, w = tid >> 5, lane = tid & 31;
    const int gid = lane >> 2, tig = lane & 3;
    const int bid = blockIdx.x;
    const int qt = bid & 31, bh = bid >> 5, h = bh & 7, b = bh >> 3;

    const float* qp = q + ((size_t)b * QLEN + (size_t)qt * QT) * INNER + h * DH;
    const size_t kvbase = (size_t)b * KLEN * INNER + h * DH;

    // zero V pad rows 77..79 in all 4 buffers (108 words each)
    if (tid < 108) {
        #pragma unroll
        for (int c = 0; c < 4; c++)
            reinterpret_cast<uint32_t*>(smc + OFF_KV + (2 * c + 1) * KV_BYTES + 77 * LDH * 2)[tid] = 0;
    }

    // prologue: stage ALL 4 chunks, one commit group per chunk (in order)
    #pragma unroll
    for (int c = 0; c < 4; c++) {
        const uint32_t kB = sbase + OFF_KV + (2 * c) * KV_BYTES;
        const uint32_t vB = kB + KV_BYTES;
        for (int i = tid; i < CL * 8; i += TPB) {
            int kk = i >> 3, d8 = (i & 7) * 8;
            size_t off = kvbase + (size_t)(c * CL + kk) * INNER + d8;
            uint32_t so = (uint32_t)(kk * LDH + d8) * 2;
            cpa16(kB + so, g_kh + off);
            cpa16(vB + so, g_vh + off);
        }
        asm volatile("cp.async.commit_group;");
    }

    // stage Q (fp16 rounded) via regular stores
    #pragma unroll
    for (int it = 0; it < 8; it++) {
        int i4 = tid + it * TPB;
        int row = i4 >> 4, dq = (i4 & 15) * 4;
        float4 t = *reinterpret_cast<const float4*>(qp + (size_t)row * INNER + dq);
        *reinterpret_cast<uint2*>(Qh + row * LDH + dq) =
            make_uint2(h2u(t.x, t.y), h2u(t.z, t.w));
    }

    const unsigned a0 = g_act[qt * QT + 16 * w + gid];
    const unsigned a1 = g_act[qt * QT + 16 * w + gid + 8];
    float csr[4];
    #pragma unroll
    for (int r = 0; r < 4; r++) csr[r] = g_cs[r];

    const int qrow  = 16 * w + (lane & 15);
    const int qcol0 = (lane >> 4) << 3;
    const int krow  = (lane & 7) + ((lane >> 4) << 3);
    const int kcol0 = ((lane >> 3) & 1) << 3;

    float O[8][4];
    #pragma unroll
    for (int n = 0; n < 8; n++)
        #pragma unroll
        for (int e = 0; e < 4; e++) O[n][e] = 0.f;
    float L0 = 0.f, L1 = 0.f;
    uint32_t qf[4][4];
    bool qload = false;

    const bool bk0 = (tig <= 2), bk1 = (tig < 2);   // chunk col 72+2tig(+1) < 77

    #pragma unroll
    for (int c = 0; c < 4; c++) {
        // wait for this chunk's group (later groups may still be in flight)
        if (c == 0)      asm volatile("cp.async.wait_group 3;");
        else if (c == 1) asm volatile("cp.async.wait_group 2;");
        else if (c == 2) asm volatile("cp.async.wait_group 1;");
        else             asm volatile("cp.async.wait_group 0;");
        __syncthreads();

        if (!qload) {    // first pass: Q fragments into registers (Q visible now)
            #pragma unroll
            for (int kt = 0; kt < 4; kt++)
                ldsm_x4(qf[kt], qh_b + (uint32_t)(qrow * LDH + 16 * kt + qcol0) * 2);
            qload = true;
        }

        const uint32_t kB = sbase + OFF_KV + (2 * c) * KV_BYTES;
        const uint32_t vB = kB + KV_BYTES;

        // ---- S = Q K^T ----
        float S[10][4];
        #pragma unroll
        for (int j = 0; j < 10; j++)
            #pragma unroll
            for (int e = 0; e < 4; e++) S[j][e] = 0.f;
        #pragma unroll
        for (int kt = 0; kt < 4; kt++) {
            #pragma unroll
            for (int np = 0; np < 5; np++) {
                uint32_t bhf[4];
                ldsm_x4(bhf, kB + (uint32_t)((16 * np + krow) * LDH + 16 * kt + kcol0) * 2);
                mma16816(S[2 * np],     qf[kt], bhf[0], bhf[1]);
                mma16816(S[2 * np + 1], qf[kt], bhf[2], bhf[3]);
            }
        }

        // ---- P = 2^(S*cf - 8), masked; accumulate L ----
        const float c2 = csr[c];
        const bool r0a = (a0 >> c) & 1, r1a = (a1 >> c) & 1;
        uint32_t pA[5][4];
        #pragma unroll
        for (int kt2 = 0; kt2 < 5; kt2++) {
            int j0 = 2 * kt2, j1 = 2 * kt2 + 1;
            bool o10 = (j1 < 9) || bk0, o11 = (j1 < 9) || bk1;
            float e00 = r0a          ? ex2(fmaf(S[j0][0], c2, -8.f)) : 0.f;
            float e01 = r0a          ? ex2(fmaf(S[j0][1], c2, -8.f)) : 0.f;
            float e02 = r1a          ? ex2(fmaf(S[j0][2], c2, -8.f)) : 0.f;
            float e03 = r1a          ? ex2(fmaf(S[j0][3], c2, -8.f)) : 0.f;
            float e10 = (r0a && o10) ? ex2(fmaf(S[j1][0], c2, -8.f)) : 0.f;
            float e11 = (r0a && o11) ? ex2(fmaf(S[j1][1], c2, -8.f)) : 0.f;
            float e12 = (r1a && o10) ? ex2(fmaf(S[j1][2], c2, -8.f)) : 0.f;
            float e13 = (r1a && o11) ? ex2(fmaf(S[j1][3], c2, -8.f)) : 0.f;
            L0 += (e00 + e01) + (e10 + e11);
            L1 += (e02 + e03) + (e12 + e13);
            pA[kt2][0] = h2u(e00, e01);
            pA[kt2][1] = h2u(e02, e03);
            pA[kt2][2] = h2u(e10, e11);
            pA[kt2][3] = h2u(e12, e13);
        }

        // ---- O += P V ----
        #pragma unroll
        for (int kt2 = 0; kt2 < 5; kt2++) {
            #pragma unroll
            for (int dp = 0; dp < 4; dp++) {
                uint32_t vf[4];
                ldsm_x4_t(vf, vB + (uint32_t)((16 * kt2 + krow) * LDH + 16 * dp + kcol0) * 2);
                mma16816(O[2 * dp],     pA[kt2], vf[0], vf[2]);
                mma16816(O[2 * dp + 1], pA[kt2], vf[1], vf[3]);
            }
        }
        // no tail barrier: buffers are never reused
    }

    // ---- final L reduction; write out ----
    L0 += __shfl_xor_sync(0xffffffffu, L0, 1);
    L0 += __shfl_xor_sync(0xffffffffu, L0, 2);
    L1 += __shfl_xor_sync(0xffffffffu, L1, 1);
    L1 += __shfl_xor_sync(0xffffffffu, L1, 2);
    const float i0 = 1.f / L0, i1 = 1.f / L1;
    float* o0 = out + ((size_t)b * QLEN + (size_t)qt * QT + 16 * w + gid) * INNER + h * DH + 2 * tig;
    float* o1 = o0 + (size_t)8 * INNER;
    #pragma unroll
    for (int n = 0; n < 8; n++) {
        *reinterpret_cast<float2*>(o0 + 8 * n) = make_float2(O[n][0] * i0, O[n][1] * i0);
        *reinterpret_cast<float2*>(o1 + 8 * n) = make_float2(O[n][2] * i1, O[n][3] * i1);
    }
}

extern "C" void kernel_launch(void* const* d_in, const int* in_sizes, int n_in,
                              void* d_out, int out_size) {
    const float* q  = (const float*)d_in[0];
    const float* k  = (const float*)d_in[1];
    const float* v  = (const float*)d_in[2];
    const float* dd = (const float*)d_in[3];
    float* out = (float*)d_out;

    prep_kernel<<<325, 256>>>(k, v, dd);

    cudaFuncSetAttribute(ddca_kernel,
                         cudaFuncAttributeMaxDynamicSharedMemorySize, SMEM_BYTES);
    ddca_kernel<<<512, TPB, SMEM_BYTES>>>(q, out);
}

// round 10
// speedup vs baseline: 1.4157x; 1.0928x over previous
#include <cuda_runtime.h>
#include <cuda_fp16.h>
#include <cstdint>

constexpr int Hh = 8, DH = 64, INNER = 512, QLEN = 4096, KLEN = 308, CL = 77, CP = 80;
constexpr int QT = 128, NQT = 32, TPB = 256;
constexpr int LDH = 72;                     // halves per smem row (144B, ldmatrix conflict-free)

// device scratch
__device__ __half g_kh[2 * KLEN * INNER];
__device__ __half g_vh[2 * KLEN * INNER];
__device__ float  g_cs[4];                  // (128/sum)*log2(e)
__device__ unsigned char g_act[QLEN];

// smem: Q (fp16) + double-buffered K/V (R7 layout)
constexpr int KV_BYTES = CP * LDH * 2;            // 11520
constexpr int OFF_QH = 0;
constexpr int OFF_K0 = OFF_QH + QT * LDH * 2;     // 18432
constexpr int OFF_V0 = OFF_K0 + KV_BYTES;
constexpr int OFF_K1 = OFF_V0 + KV_BYTES;
constexpr int OFF_V1 = OFF_K1 + KV_BYTES;
constexpr int SMEM_BYTES = OFF_V1 + KV_BYTES;     // 64512 -> fits 3 CTAs/SM

__device__ __forceinline__ uint32_t h2u(float a, float b) {
    __half2 h = __floats2half2_rn(a, b);
    return *reinterpret_cast<uint32_t*>(&h);
}
__device__ __forceinline__ float ex2(float x) {
    float r; asm("ex2.approx.f32 %0, %1;" : "=f"(r) : "f"(x)); return r;
}
__device__ __forceinline__ void ldsm_x4(uint32_t* r, uint32_t addr) {
    asm volatile("ldmatrix.sync.aligned.m8n8.x4.shared.b16 {%0,%1,%2,%3}, [%4];"
                 : "=r"(r[0]), "=r"(r[1]), "=r"(r[2]), "=r"(r[3]) : "r"(addr));
}
__device__ __forceinline__ void ldsm_x4_t(uint32_t* r, uint32_t addr) {
    asm volatile("ldmatrix.sync.aligned.m8n8.x4.trans.shared.b16 {%0,%1,%2,%3}, [%4];"
                 : "=r"(r[0]), "=r"(r[1]), "=r"(r[2]), "=r"(r[3]) : "r"(addr));
}
__device__ __forceinline__ void mma16816(float* c, const uint32_t* a, uint32_t b0, uint32_t b1) {
    asm volatile("mma.sync.aligned.m16n8k16.row.col.f32.f16.f16.f32 "
                 "{%0,%1,%2,%3},{%4,%5,%6,%7},{%8,%9},{%0,%1,%2,%3};"
                 : "+f"(c[0]), "+f"(c[1]), "+f"(c[2]), "+f"(c[3])
                 : "r"(a[0]), "r"(a[1]), "r"(a[2]), "r"(a[3]), "r"(b0), "r"(b1));
}
__device__ __forceinline__ void cpa16(uint32_t s, const void* g) {
    asm volatile("cp.async.cg.shared.global [%0], [%1], 16;" :: "r"(s), "l"(g));
}

// ---------------------------------------------------------------------------
// prep: K,V -> fp16; region scales (x log2e); per-query activity bytes
// ---------------------------------------------------------------------------
__global__ void __launch_bounds__(256) prep_kernel(const float* __restrict__ k,
                                                   const float* __restrict__ v,
                                                   const float* __restrict__ dd)
{
    int blk = blockIdx.x, tid = threadIdx.x;
    if (blk < 308) {
        int idx = (blk * 256 + tid) * 4;               // over 2*308*512 floats
        float4 kf = *reinterpret_cast<const float4*>(k + idx);
        float4 vf = *reinterpret_cast<const float4*>(v + idx);
        *reinterpret_cast<uint2*>(reinterpret_cast<char*>(g_kh) + (size_t)idx * 2) =
            make_uint2(h2u(kf.x, kf.y), h2u(kf.z, kf.w));
        *reinterpret_cast<uint2*>(reinterpret_cast<char*>(g_vh) + (size_t)idx * 2) =
            make_uint2(h2u(vf.x, vf.y), h2u(vf.z, vf.w));
    } else if (blk == 308) {
        __shared__ float ws[4][8];
        int w = tid >> 5, l = tid & 31;
        #pragma unroll
        for (int r = 0; r < 4; r++) {
            float s = 0.f;
            #pragma unroll
            for (int i = 0; i < 4; i++) s += dd[r * 1024 + i * 256 + tid];
            #pragma unroll
            for (int o = 16; o > 0; o >>= 1) s += __shfl_xor_sync(0xffffffffu, s, o, 32);
            if (l == 0) ws[r][w] = s;
        }
        __syncthreads();
        if (tid < 4) {
            float s = 0.f;
            #pragma unroll
            for (int ww = 0; ww < 8; ww++) s += ws[tid][ww];
            g_cs[tid] = (128.f / s) * 1.4426950408889634f;
        }
    } else {
        int qg = (blk - 309) * 256 + tid;              // 16 blocks -> 4096
        int y = qg >> 6, x = qg & 63;
        unsigned a = 0;
        #pragma unroll
        for (int r = 0; r < 4; r++)
            if (dd[r * 1024 + (y >> 1) * 32 + (x >> 1)] > 0.5f) a |= 1u << r;
        g_act[qg] = (unsigned char)a;
    }
}

// ---------------------------------------------------------------------------
// main: fp16 MMA attention; R7 double-buffered staging; np-streamed compute
// (small live register set) -> 3 CTAs/SM
// ---------------------------------------------------------------------------
__global__ void __launch_bounds__(TPB, 3)
ddca_kernel(const float* __restrict__ q, float* __restrict__ out)
{
    extern __shared__ char smc[];
    half* Qh = (half*)(smc + OFF_QH);
    uint32_t sbase = (uint32_t)__cvta_generic_to_shared(smc);
    const uint32_t qh_b = sbase + OFF_QH;
    const uint32_t kb[2] = {sbase + OFF_K0, sbase + OFF_K1};
    const uint32_t vb[2] = {sbase + OFF_V0, sbase + OFF_V1};

    const int tid = threadIdx.x, w = tid >> 5, lane = tid & 31;
    const int gid = lane >> 2, tig = lane & 3;
    const int bid = blockIdx.x;
    const int qt = bid & 31, bh = bid >> 5, h = bh & 7, b = bh >> 3;

    const float* qp = q + ((size_t)b * QLEN + (size_t)qt * QT) * INNER + h * DH;
    const size_t kvbase = (size_t)b * KLEN * INNER + h * DH;

    // zero V pad rows 77..79 in both buffers
    if (tid < 108) {
        reinterpret_cast<uint32_t*>(smc + OFF_V0 + 77 * LDH * 2)[tid] = 0;
        reinterpret_cast<uint32_t*>(smc + OFF_V1 + 77 * LDH * 2)[tid] = 0;
    }

    // prologue: stage chunk 0 K/V via cp.async
    for (int i = tid; i < CL * 8; i += TPB) {
        int kk = i >> 3, d8 = (i & 7) * 8;
        size_t off = kvbase + (size_t)kk * INNER + d8;
        uint32_t so = (uint32_t)(kk * LDH + d8) * 2;
        cpa16(kb[0] + so, g_kh + off);
        cpa16(vb[0] + so, g_vh + off);
    }
    asm volatile("cp.async.commit_group;");

    // stage Q (fp16 rounded)
    #pragma unroll
    for (int it = 0; it < 8; it++) {
        int i4 = tid + it * TPB;
        int row = i4 >> 4, dq = (i4 & 15) * 4;
        float4 t = *reinterpret_cast<const float4*>(qp + (size_t)row * INNER + dq);
        *reinterpret_cast<uint2*>(Qh + row * LDH + dq) =
            make_uint2(h2u(t.x, t.y), h2u(t.z, t.w));
    }

    const unsigned a0 = g_act[qt * QT + 16 * w + gid];
    const unsigned a1 = g_act[qt * QT + 16 * w + gid + 8];
    float csr[4];
    #pragma unroll
    for (int r = 0; r < 4; r++) csr[r] = g_cs[r];

    const int qrow  = 16 * w + (lane & 15);
    const int qcol0 = (lane >> 4) << 3;
    const int krow  = (lane & 7) + ((lane >> 4) << 3);
    const int kcol0 = ((lane >> 3) & 1) << 3;

    float O[8][4];
    #pragma unroll
    for (int n = 0; n < 8; n++)
        #pragma unroll
        for (int e = 0; e < 4; e++) O[n][e] = 0.f;
    float L0 = 0.f, L1 = 0.f;
    uint32_t qf[4][4];
    bool qload = false;

    const bool bk0 = (tig <= 2), bk1 = (tig < 2);   // chunk col 72+2tig(+1) < 77

    #pragma unroll 1
    for (int c = 0; c < 4; c++) {
        // stage next chunk into the other buffer; wait for current
        if (c < 3) {
            int nb = (c + 1) & 1;
            for (int i = tid; i < CL * 8; i += TPB) {
                int kk = i >> 3, d8 = (i & 7) * 8;
                size_t off = kvbase + (size_t)((c + 1) * CL + kk) * INNER + d8;
                uint32_t so = (uint32_t)(kk * LDH + d8) * 2;
                cpa16(kb[nb] + so, g_kh + off);
                cpa16(vb[nb] + so, g_vh + off);
            }
            asm volatile("cp.async.commit_group;");
            asm volatile("cp.async.wait_group 1;");
        } else {
            asm volatile("cp.async.wait_group 0;");
        }
        __syncthreads();
        const uint32_t khc = kb[c & 1], vc = vb[c & 1];

        if (!qload) {   // Q visible after first barrier; fragments live all chunks
            #pragma unroll
            for (int kt = 0; kt < 4; kt++)
                ldsm_x4(qf[kt], qh_b + (uint32_t)(qrow * LDH + 16 * kt + qcol0) * 2);
            qload = true;
        }

        const float c2 = csr[c];
        const bool r0a = (a0 >> c) & 1, r1a = (a1 >> c) & 1;

        // ---- streamed per-16-key tile: S-tile -> exp -> O += P V ----
        #pragma unroll
        for (int np = 0; np < 5; np++) {
            float S0[4] = {0.f, 0.f, 0.f, 0.f};
            float S1[4] = {0.f, 0.f, 0.f, 0.f};
            #pragma unroll
            for (int kt = 0; kt < 4; kt++) {
                uint32_t bhf[4];
                ldsm_x4(bhf, khc + (uint32_t)((16 * np + krow) * LDH + 16 * kt + kcol0) * 2);
                mma16816(S0, qf[kt], bhf[0], bhf[1]);
                mma16816(S1, qf[kt], bhf[2], bhf[3]);
            }

            const bool o10 = (np < 4) || bk0, o11 = (np < 4) || bk1;
            float e00 = r0a          ? ex2(fmaf(S0[0], c2, -8.f)) : 0.f;
            float e01 = r0a          ? ex2(fmaf(S0[1], c2, -8.f)) : 0.f;
            float e02 = r1a          ? ex2(fmaf(S0[2], c2, -8.f)) : 0.f;
            float e03 = r1a          ? ex2(fmaf(S0[3], c2, -8.f)) : 0.f;
            float e10 = (r0a && o10) ? ex2(fmaf(S1[0], c2, -8.f)) : 0.f;
            float e11 = (r0a && o11) ? ex2(fmaf(S1[1], c2, -8.f)) : 0.f;
            float e12 = (r1a && o10) ? ex2(fmaf(S1[2], c2, -8.f)) : 0.f;
            float e13 = (r1a && o11) ? ex2(fmaf(S1[3], c2, -8.f)) : 0.f;
            L0 += (e00 + e01) + (e10 + e11);
            L1 += (e02 + e03) + (e12 + e13);
            uint32_t pA[4];
            pA[0] = h2u(e00, e01);
            pA[1] = h2u(e02, e03);
            pA[2] = h2u(e10, e11);
            pA[3] = h2u(e12, e13);

            #pragma unroll
            for (int dp = 0; dp < 4; dp++) {
                uint32_t vf[4];
                ldsm_x4_t(vf, vc + (uint32_t)((16 * np + krow) * LDH + 16 * dp + kcol0) * 2);
                mma16816(O[2 * dp],     pA, vf[0], vf[2]);
                mma16816(O[2 * dp + 1], pA, vf[1], vf[3]);
            }
        }
        __syncthreads();   // buffer c&1 free before restage
    }

    // ---- final L reduction; write out ----
    L0 += __shfl_xor_sync(0xffffffffu, L0, 1);
    L0 += __shfl_xor_sync(0xffffffffu, L0, 2);
    L1 += __shfl_xor_sync(0xffffffffu, L1, 1);
    L1 += __shfl_xor_sync(0xffffffffu, L1, 2);
    const float i0 = 1.f / L0, i1 = 1.f / L1;
    float* o0 = out + ((size_t)b * QLEN + (size_t)qt * QT + 16 * w + gid) * INNER + h * DH + 2 * tig;
    float* o1 = o0 + (size_t)8 * INNER;
    #pragma unroll
    for (int n = 0; n < 8; n++) {
        *reinterpret_cast<float2*>(o0 + 8 * n) = make_float2(O[n][0] * i0, O[n][1] * i0);
        *reinterpret_cast<float2*>(o1 + 8 * n) = make_float2(O[n][2] * i1, O[n][3] * i1);
    }
}

extern "C" void kernel_launch(void* const* d_in, const int* in_sizes, int n_in,
                              void* d_out, int out_size) {
    const float* q  = (const float*)d_in[0];
    const float* k  = (const float*)d_in[1];
    const float* v  = (const float*)d_in[2];
    const float* dd = (const float*)d_in[3];
    float* out = (float*)d_out;

    prep_kernel<<<325, 256>>>(k, v, dd);

    cudaFuncSetAttribute(ddca_kernel,
                         cudaFuncAttributeMaxDynamicSharedMemorySize, SMEM_BYTES);
    ddca_kernel<<<512, TPB, SMEM_BYTES>>>(q, out);
}

// round 11
// speedup vs baseline: 1.4585x; 1.0302x over previous
#include <cuda_runtime.h>
#include <cuda_fp16.h>
#include <cstdint>

constexpr int Hh = 8, DH = 64, INNER = 512, QLEN = 4096, KLEN = 308, CL = 77, CP = 80;
constexpr int QT = 64, NQT = QLEN / QT;     // 64 query tiles of 64 rows
constexpr int TPB = 128;                    // 4 warps
constexpr int LDH = 72;                     // halves per smem row (144B, ldmatrix conflict-free)

// device scratch
__device__ __half g_kh[2 * KLEN * INNER];
__device__ __half g_vh[2 * KLEN * INNER];
__device__ float  g_cs[4];                  // (128/sum)*log2(e)
__device__ unsigned char g_act[QLEN];

// smem: Q (fp16, 64 rows) + single K/V chunk buffer
constexpr int KV_BYTES = CP * LDH * 2;            // 11520
constexpr int OFF_QH = 0;
constexpr int OFF_K  = OFF_QH + QT * LDH * 2;     // 9216
constexpr int OFF_V  = OFF_K + KV_BYTES;          // 20736
constexpr int SMEM_BYTES = OFF_V + KV_BYTES;      // 32256 -> occ 6 (reg-capped)

__device__ __forceinline__ uint32_t h2u(float a, float b) {
    __half2 h = __floats2half2_rn(a, b);
    return *reinterpret_cast<uint32_t*>(&h);
}
__device__ __forceinline__ float ex2(float x) {
    float r; asm("ex2.approx.f32 %0, %1;" : "=f"(r) : "f"(x)); return r;
}
__device__ __forceinline__ void ldsm_x4(uint32_t* r, uint32_t addr) {
    asm volatile("ldmatrix.sync.aligned.m8n8.x4.shared.b16 {%0,%1,%2,%3}, [%4];"
                 : "=r"(r[0]), "=r"(r[1]), "=r"(r[2]), "=r"(r[3]) : "r"(addr));
}
__device__ __forceinline__ void ldsm_x4_t(uint32_t* r, uint32_t addr) {
    asm volatile("ldmatrix.sync.aligned.m8n8.x4.trans.shared.b16 {%0,%1,%2,%3}, [%4];"
                 : "=r"(r[0]), "=r"(r[1]), "=r"(r[2]), "=r"(r[3]) : "r"(addr));
}
__device__ __forceinline__ void mma16816(float* c, const uint32_t* a, uint32_t b0, uint32_t b1) {
    asm volatile("mma.sync.aligned.m16n8k16.row.col.f32.f16.f16.f32 "
                 "{%0,%1,%2,%3},{%4,%5,%6,%7},{%8,%9},{%0,%1,%2,%3};"
                 : "+f"(c[0]), "+f"(c[1]), "+f"(c[2]), "+f"(c[3])
                 : "r"(a[0]), "r"(a[1]), "r"(a[2]), "r"(a[3]), "r"(b0), "r"(b1));
}
__device__ __forceinline__ void cpa16(uint32_t s, const void* g) {
    asm volatile("cp.async.cg.shared.global [%0], [%1], 16;" :: "r"(s), "l"(g));
}

// ---------------------------------------------------------------------------
// prep: K,V -> fp16; region scales (x log2e); per-query activity bytes
// ---------------------------------------------------------------------------
__global__ void __launch_bounds__(256) prep_kernel(const float* __restrict__ k,
                                                   const float* __restrict__ v,
                                                   const float* __restrict__ dd)
{
    int blk = blockIdx.x, tid = threadIdx.x;
    if (blk < 308) {
        int idx = (blk * 256 + tid) * 4;               // over 2*308*512 floats
        float4 kf = *reinterpret_cast<const float4*>(k + idx);
        float4 vf = *reinterpret_cast<const float4*>(v + idx);
        *reinterpret_cast<uint2*>(reinterpret_cast<char*>(g_kh) + (size_t)idx * 2) =
            make_uint2(h2u(kf.x, kf.y), h2u(kf.z, kf.w));
        *reinterpret_cast<uint2*>(reinterpret_cast<char*>(g_vh) + (size_t)idx * 2) =
            make_uint2(h2u(vf.x, vf.y), h2u(vf.z, vf.w));
    } else if (blk == 308) {
        __shared__ float ws[4][8];
        int w = tid >> 5, l = tid & 31;
        #pragma unroll
        for (int r = 0; r < 4; r++) {
            float s = 0.f;
            #pragma unroll
            for (int i = 0; i < 4; i++) s += dd[r * 1024 + i * 256 + tid];
            #pragma unroll
            for (int o = 16; o > 0; o >>= 1) s += __shfl_xor_sync(0xffffffffu, s, o, 32);
            if (l == 0) ws[r][w] = s;
        }
        __syncthreads();
        if (tid < 4) {
            float s = 0.f;
            #pragma unroll
            for (int ww = 0; ww < 8; ww++) s += ws[tid][ww];
            g_cs[tid] = (128.f / s) * 1.4426950408889634f;
        }
    } else {
        int qg = (blk - 309) * 256 + tid;              // 16 blocks -> 4096
        int y = qg >> 6, x = qg & 63;
        unsigned a = 0;
        #pragma unroll
        for (int r = 0; r < 4; r++)
            if (dd[r * 1024 + (y >> 1) * 32 + (x >> 1)] > 0.5f) a |= 1u << r;
        g_act[qg] = (unsigned char)a;
    }
}

// ---------------------------------------------------------------------------
// main: fp16 MMA attention; small CTAs (M=64, 4 warps) for near-perfect wave
// balance at occ 6; single K/V buffer restaged per chunk
// ---------------------------------------------------------------------------
__global__ void __launch_bounds__(TPB, 6)
ddca_kernel(const float* __restrict__ q, float* __restrict__ out)
{
    extern __shared__ char smc[];
    half* Qh = (half*)(smc + OFF_QH);
    uint32_t sbase = (uint32_t)__cvta_generic_to_shared(smc);
    const uint32_t qh_b = sbase + OFF_QH;
    const uint32_t k_b  = sbase + OFF_K;
    const uint32_t v_b  = sbase + OFF_V;

    const int tid = threadIdx.x, w = tid >> 5, lane = tid & 31;
    const int gid = lane >> 2, tig = lane & 3;
    const int bid = blockIdx.x;
    const int qt = bid & 63, bh = bid >> 6, h = bh & 7, b = bh >> 3;

    const float* qp = q + ((size_t)b * QLEN + (size_t)qt * QT) * INNER + h * DH;
    const size_t kvbase = (size_t)b * KLEN * INNER + h * DH;

    // zero V pad rows 77..79 (masked in P, but avoid NaN from poison)
    if (tid < 108)
        reinterpret_cast<uint32_t*>(smc + OFF_V + 77 * LDH * 2)[tid] = 0;

    // prologue: stage chunk 0 K/V
    for (int i = tid; i < CL * 8; i += TPB) {
        int kk = i >> 3, d8 = (i & 7) * 8;
        size_t off = kvbase + (size_t)kk * INNER + d8;
        uint32_t so = (uint32_t)(kk * LDH + d8) * 2;
        cpa16(k_b + so, g_kh + off);
        cpa16(v_b + so, g_vh + off);
    }
    asm volatile("cp.async.commit_group;");

    // stage Q (fp16 rounded): 64 rows x 16 groups = 1024 / 128 thr = 8 iters
    #pragma unroll
    for (int it = 0; it < 8; it++) {
        int i4 = tid + it * TPB;
        int row = i4 >> 4, dq = (i4 & 15) * 4;
        float4 t = *reinterpret_cast<const float4*>(qp + (size_t)row * INNER + dq);
        *reinterpret_cast<uint2*>(Qh + row * LDH + dq) =
            make_uint2(h2u(t.x, t.y), h2u(t.z, t.w));
    }

    const unsigned a0 = g_act[qt * QT + 16 * w + gid];
    const unsigned a1 = g_act[qt * QT + 16 * w + gid + 8];
    float csr[4];
    #pragma unroll
    for (int r = 0; r < 4; r++) csr[r] = g_cs[r];

    const int qrow  = 16 * w + (lane & 15);
    const int qcol0 = (lane >> 4) << 3;
    const int krow  = (lane & 7) + ((lane >> 4) << 3);
    const int kcol0 = ((lane >> 3) & 1) << 3;

    float O[8][4];
    #pragma unroll
    for (int n = 0; n < 8; n++)
        #pragma unroll
        for (int e = 0; e < 4; e++) O[n][e] = 0.f;
    float L0 = 0.f, L1 = 0.f;
    uint32_t qf[4][4];
    bool qload = false;

    const bool bk0 = (tig <= 2), bk1 = (tig < 2);   // chunk col 72+2tig(+1) < 77

    #pragma unroll 1
    for (int c = 0; c < 4; c++) {
        asm volatile("cp.async.wait_group 0;");
        __syncthreads();                      // K/V chunk c (and Q on c=0) visible

        if (!qload) {
            #pragma unroll
            for (int kt = 0; kt < 4; kt++)
                ldsm_x4(qf[kt], qh_b + (uint32_t)(qrow * LDH + 16 * kt + qcol0) * 2);
            qload = true;
        }

        const float c2 = csr[c];
        const bool r0a = (a0 >> c) & 1, r1a = (a1 >> c) & 1;

        // ---- streamed per-16-key tile: S-tile -> exp -> O += P V ----
        #pragma unroll
        for (int np = 0; np < 5; np++) {
            float S0[4] = {0.f, 0.f, 0.f, 0.f};
            float S1[4] = {0.f, 0.f, 0.f, 0.f};
            #pragma unroll
            for (int kt = 0; kt < 4; kt++) {
                uint32_t bhf[4];
                ldsm_x4(bhf, k_b + (uint32_t)((16 * np + krow) * LDH + 16 * kt + kcol0) * 2);
                mma16816(S0, qf[kt], bhf[0], bhf[1]);
                mma16816(S1, qf[kt], bhf[2], bhf[3]);
            }

            const bool o10 = (np < 4) || bk0, o11 = (np < 4) || bk1;
            float e00 = r0a          ? ex2(fmaf(S0[0], c2, -8.f)) : 0.f;
            float e01 = r0a          ? ex2(fmaf(S0[1], c2, -8.f)) : 0.f;
            float e02 = r1a          ? ex2(fmaf(S0[2], c2, -8.f)) : 0.f;
            float e03 = r1a          ? ex2(fmaf(S0[3], c2, -8.f)) : 0.f;
            float e10 = (r0a && o10) ? ex2(fmaf(S1[0], c2, -8.f)) : 0.f;
            float e11 = (r0a && o11) ? ex2(fmaf(S1[1], c2, -8.f)) : 0.f;
            float e12 = (r1a && o10) ? ex2(fmaf(S1[2], c2, -8.f)) : 0.f;
            float e13 = (r1a && o11) ? ex2(fmaf(S1[3], c2, -8.f)) : 0.f;
            L0 += (e00 + e01) + (e10 + e11);
            L1 += (e02 + e03) + (e12 + e13);
            uint32_t pA[4];
            pA[0] = h2u(e00, e01);
            pA[1] = h2u(e02, e03);
            pA[2] = h2u(e10, e11);
            pA[3] = h2u(e12, e13);

            #pragma unroll
            for (int dp = 0; dp < 4; dp++) {
                uint32_t vf[4];
                ldsm_x4_t(vf, v_b + (uint32_t)((16 * np + krow) * LDH + 16 * dp + kcol0) * 2);
                mma16816(O[2 * dp],     pA, vf[0], vf[2]);
                mma16816(O[2 * dp + 1], pA, vf[1], vf[3]);
            }
        }

        // restage buffer with next chunk (all 4 warps done reading)
        if (c < 3) {
            __syncthreads();
            for (int i = tid; i < CL * 8; i += TPB) {
                int kk = i >> 3, d8 = (i & 7) * 8;
                size_t off = kvbase + (size_t)((c + 1) * CL + kk) * INNER + d8;
                uint32_t so = (uint32_t)(kk * LDH + d8) * 2;
                cpa16(k_b + so, g_kh + off);
                cpa16(v_b + so, g_vh + off);
            }
            asm volatile("cp.async.commit_group;");
        }
    }

    // ---- final L reduction; write out ----
    L0 += __shfl_xor_sync(0xffffffffu, L0, 1);
    L0 += __shfl_xor_sync(0xffffffffu, L0, 2);
    L1 += __shfl_xor_sync(0xffffffffu, L1, 1);
    L1 += __shfl_xor_sync(0xffffffffu, L1, 2);
    const float i0 = 1.f / L0, i1 = 1.f / L1;
    float* o0 = out + ((size_t)b * QLEN + (size_t)qt * QT + 16 * w + gid) * INNER + h * DH + 2 * tig;
    float* o1 = o0 + (size_t)8 * INNER;
    #pragma unroll
    for (int n = 0; n < 8; n++) {
        *reinterpret_cast<float2*>(o0 + 8 * n) = make_float2(O[n][0] * i0, O[n][1] * i0);
        *reinterpret_cast<float2*>(o1 + 8 * n) = make_float2(O[n][2] * i1, O[n][3] * i1);
    }
}

extern "C" void kernel_launch(void* const* d_in, const int* in_sizes, int n_in,
                              void* d_out, int out_size) {
    const float* q  = (const float*)d_in[0];
    const float* k  = (const float*)d_in[1];
    const float* v  = (const float*)d_in[2];
    const float* dd = (const float*)d_in[3];
    float* out = (float*)d_out;

    prep_kernel<<<325, 256>>>(k, v, dd);

    cudaFuncSetAttribute(ddca_kernel,
                         cudaFuncAttributeMaxDynamicSharedMemorySize, SMEM_BYTES);
    ddca_kernel<<<2 * Hh * NQT, TPB, SMEM_BYTES>>>(q, out);   // 1024 CTAs
}